// round 12
// baseline (speedup 1.0000x reference)
#include <cuda_runtime.h>
#include <cuda_bf16.h>

// AUGRU, B=65536, T=50, E=10.
// R8: remove ALL inline asm. R5/R7 both spilled ~5-8KB/thread to local memory;
// the common factor was the fma.rn.f32x2 inline-asm blocks, whose .b64
// even/odd register-pair alignment constraints (x ~1200 per loop body) blow up
// ptxas register allocation. This round is pure scalar fmaf: nothing can spill.
//  - Dense compositions folded once per launch (9 -> 6 matvecs/step).
//  - 1 batch element per thread (65536 threads, one wave, ~443 thr/SM).
//  - Folded weights in smem, layout [g][j][i], 80B contiguous rows.
//  - x and attention read as 2-step 80B chunks = 5 aligned float4 each.

#define NB 65536
#define NT 50
#define NE 10
#define TPB 128
#define NBLK (NB / TPB)   // 512 blocks

// Folded params, 630 floats:
//  [0,600):  sW[g][j][i]  (g gate, j output col, i stacked input row:
//            i 0..9 = x-side A_g = W1x_g @ W2_g, i 10..19 = h-side B_g)
//  [600,630): bias c[g][j] = b1_g @ W2_g + b2_g
__device__ __align__(16) float g_fold[630];

// ---------------------------------------------------------------- fold kernel
__global__ void fold_k(
    const float* __restrict__ Wi_r, const float* __restrict__ bi_r,
    const float* __restrict__ Wh_r, const float* __restrict__ Ws_r,
    const float* __restrict__ bs_r,
    const float* __restrict__ Wi_z, const float* __restrict__ bi_z,
    const float* __restrict__ Wh_z, const float* __restrict__ Ws_z,
    const float* __restrict__ bs_z,
    const float* __restrict__ Wi_h, const float* __restrict__ bi_h,
    const float* __restrict__ Wh_h, const float* __restrict__ Wt_h,
    const float* __restrict__ bt_h)
{
    for (int idx = threadIdx.x; idx < 630; idx += blockDim.x) {
        if (idx < 600) {
            int g = idx / 200;
            int r = idx % 200;
            int j = r / 20;
            int i = r % 20;
            const float* w2 = (g == 0) ? Ws_r : (g == 1) ? Ws_z : Wt_h;
            const float* w1;
            if (i < 10) {
                const float* wx = (g == 0) ? Wi_r : (g == 1) ? Wi_z : Wi_h;
                w1 = wx + i * 10;
            } else {
                const float* wh = (g == 0) ? Wh_r : (g == 1) ? Wh_z : Wh_h;
                w1 = wh + (i - 10) * 10;
            }
            float s = 0.0f;
#pragma unroll
            for (int k = 0; k < 10; k++) s += w1[k] * w2[k * 10 + j];
            g_fold[idx] = s;                     // sW[g*200 + j*20 + i]
        } else {
            int r = idx - 600;
            int g = r / 10;
            int j = r % 10;
            const float* w2 = (g == 0) ? Ws_r : (g == 1) ? Ws_z : Wt_h;
            const float* b1 = (g == 0) ? bi_r : (g == 1) ? bi_z : bi_h;
            const float* b2 = (g == 0) ? bs_r : (g == 1) ? bs_z : bt_h;
            float s = b2[j];
#pragma unroll
            for (int k = 0; k < 10; k++) s += b1[k] * w2[k * 10 + j];
            g_fold[idx] = s;                     // sC[g*10 + j]
        }
    }
}

// ---------------------------------------------------------------- activations
__device__ __forceinline__ float sigf(float u) {
    float e = __expf(-u);                 // FMUL + MUFU.EX2
    return __fdividef(1.0f, 1.0f + e);    // FADD + MUFU.RCP + FMUL
}
__device__ __forceinline__ float tanhfast(float u) {
    float e = __expf(2.0f * u);           // saturates correctly at +-inf
    return 1.0f - __fdividef(2.0f, e + 1.0f);
}

// ---------------------------------------------------------------- one gate
// o[j] = act( c[g][j] + sum_{i<10} x[i]*W[g][j][i] + sum_{i<10} v[i]*W[g][j][10+i] )
// x, v, o are register arrays; every index is a compile-time constant.
template <int ACT, int G>
__device__ __forceinline__ void gate1(
    const float* __restrict__ sW, const float* __restrict__ sC,
    const float (&x)[10], const float (&v)[10], float (&o)[10])
{
#pragma unroll
    for (int j = 0; j < 10; j++) {
        float acc = sC[G * 10 + j];
#pragma unroll
        for (int i = 0; i < 20; i++) {
            float w  = sW[G * 200 + j * 20 + i];
            float xi = (i < 10) ? x[i] : v[i - 10];   // compile-time select
            acc = fmaf(xi, w, acc);
        }
        o[j] = (ACT == 0) ? sigf(acc) : tanhfast(acc);
    }
}

// ---------------------------------------------------------------- one timestep
template <int S>   // which half of the 2-step chunk
__device__ __forceinline__ void do_step(
    const float* __restrict__ sW, const float* __restrict__ sC,
    const float (&xc)[20], const float (&ac)[20], float (&h)[10])
{
    float x[10];
#pragma unroll
    for (int k = 0; k < 10; k++) x[k] = xc[S * 10 + k];

    float r[10], z[10];
    gate1<0, 0>(sW, sC, x, h, r);       // r = sigma(xA_r + hB_r + c_r)
    gate1<0, 1>(sW, sC, x, h, z);       // z = sigma(xA_z + hB_z + c_z)

    float q[10];
#pragma unroll
    for (int k = 0; k < 10; k++) q[k] = h[k] * z[k];

    float hc[10];
    gate1<1, 2>(sW, sC, x, q, hc);      // hc = tanh(xA_h + (h.z)B_h + c_h)

#pragma unroll
    for (int k = 0; k < 10; k++) {
        float Ra = ac[S * 10 + k] * r[k];
        h[k] = fmaf(Ra, hc[k] - h[k], h[k]);   // h + Ra*(hc-h)
    }
}

// ---------------------------------------------------------------- scan kernel
__global__ void __launch_bounds__(TPB) scan_k(
    const float* __restrict__ X, const float* __restrict__ Aatt,
    const float* __restrict__ H0, float* __restrict__ O)
{
    __shared__ __align__(16) float sF[630];
    for (int i = threadIdx.x; i < 630; i += TPB) sF[i] = g_fold[i];
    __syncthreads();
    const float* sW = sF;
    const float* sC = sF + 600;

    const int e = blockIdx.x * TPB + threadIdx.x;

    const float4* xq = (const float4*)(X    + (size_t)e * (NT * NE));
    const float4* aq = (const float4*)(Aatt + (size_t)e * (NT * NE));

    float h[10];
#pragma unroll
    for (int k = 0; k < 10; k++) h[k] = __ldg(H0 + k);   // broadcast init

#pragma unroll 1
    for (int c = 0; c < NT / 2; c++) {   // 2 steps/chunk: 80B = 5 aligned float4
        float xc[20], ac[20];
#pragma unroll
        for (int q = 0; q < 5; q++) {
            float4 v = __ldg(xq + c * 5 + q);
            xc[4 * q + 0] = v.x; xc[4 * q + 1] = v.y;
            xc[4 * q + 2] = v.z; xc[4 * q + 3] = v.w;
            float4 w = __ldg(aq + c * 5 + q);
            ac[4 * q + 0] = w.x; ac[4 * q + 1] = w.y;
            ac[4 * q + 2] = w.z; ac[4 * q + 3] = w.w;
        }
        do_step<0>(sW, sC, xc, ac, h);
        do_step<1>(sW, sC, xc, ac, h);
    }

    // write h_final [B, E]
    float2* op = (float2*)(O + (size_t)e * NE);
#pragma unroll
    for (int k = 0; k < 5; k++) op[k] = make_float2(h[2 * k], h[2 * k + 1]);
}

// ---------------------------------------------------------------- launch
extern "C" void kernel_launch(void* const* d_in, const int* in_sizes, int n_in,
                              void* d_out, int out_size)
{
    const float* X  = (const float*)d_in[0];
    const float* Aa = (const float*)d_in[1];
    const float* H0 = (const float*)d_in[2];

    fold_k<<<1, 256>>>(
        (const float*)d_in[3],  (const float*)d_in[4],  (const float*)d_in[5],
        (const float*)d_in[6],  (const float*)d_in[7],
        (const float*)d_in[8],  (const float*)d_in[9],  (const float*)d_in[10],
        (const float*)d_in[11], (const float*)d_in[12],
        (const float*)d_in[13], (const float*)d_in[14], (const float*)d_in[15],
        (const float*)d_in[16], (const float*)d_in[17]);

    scan_k<<<NBLK, TPB>>>(X, Aa, H0, (float*)d_out);
}